// round 10
// baseline (speedup 1.0000x reference)
#include <cuda_runtime.h>

#define NN 256
#define TT 1500
#define R 4
#define CT (32 * R)                  // 128 steps per warp-chunk
#define NCHUNK ((TT + CT - 1) / CT)  // 12 (tail: lanes 0..22 active)

// q[s][n][t] = 0.3125 - 0.075*g_max[s][n]*sat(u_s[n][t]); a_ij(t) = q0+q1
__device__ __align__(16) float g_q[2][NN * TT];

__global__ __launch_bounds__(256) void prep_kernel(const float* __restrict__ u0,
                                                   const float* __restrict__ u1,
                                                   const float* __restrict__ ksyn) {
    int g = blockIdx.x * 256 + threadIdx.x;      // float4 index
    if (g >= NN * TT / 4) return;
    int n = (g * 4) / TT;                        // TT%4==0 -> same row

    float k0 = ksyn[n];
    float c0 = 0.075f * k0 / (20.0f - 2.0f * k0);
    float4 a = ((const float4*)u0)[g];
    float4 r0;
    r0.x = fmaf(-c0, __saturatef(a.x), 0.3125f);
    r0.y = fmaf(-c0, __saturatef(a.y), 0.3125f);
    r0.z = fmaf(-c0, __saturatef(a.z), 0.3125f);
    r0.w = fmaf(-c0, __saturatef(a.w), 0.3125f);
    ((float4*)g_q[0])[g] = r0;

    float k1 = ksyn[NN + n];
    float c1 = 0.075f * k1 / (20.0f - 2.0f * k1);
    float4 b = ((const float4*)u1)[g];
    float4 r1;
    r1.x = fmaf(-c1, __saturatef(b.x), 0.3125f);
    r1.y = fmaf(-c1, __saturatef(b.y), 0.3125f);
    r1.z = fmaf(-c1, __saturatef(b.z), 0.3125f);
    r1.w = fmaf(-c1, __saturatef(b.w), 0.3125f);
    ((float4*)g_q[1])[g] = r1;
}

// One cell's 128-step chunk, 6 shfl total. Carry-baked truncated scan
// (window 8 lanes = 32 steps; dropped terms <= 0.625^32 ~ 3e-7); the final
// rotate shfl delivers v_start to lanes 1..31 AND the new carry (B_31) to
// lane 0 in a single instruction (only lane 0 ever reads `carry`).
__device__ __forceinline__ void cell_chunk(const float4 x, const float4 y,
                                           const bool act, const int lane,
                                           float& carry, float* __restrict__ o,
                                           const int t) {
    float a0, a1, a2, a3, A, B;
    if (act) {
        a0 = x.x + y.x;  a1 = x.y + y.y;  a2 = x.z + y.z;  a3 = x.w + y.w;
        A = a0; B = fmaf(-20.0f, a0, 12.5f);
        B = fmaf(a1, B, fmaf(-20.0f, a1, 12.5f)); A *= a1;
        B = fmaf(a2, B, fmaf(-20.0f, a2, 12.5f)); A *= a2;
        B = fmaf(a3, B, fmaf(-20.0f, a3, 12.5f)); A *= a3;
    } else {
        A = 1.0f; B = 0.0f;
        a0 = a1 = a2 = a3 = 1.0f;
    }

    // bake chunk carry into lane 0's map
    if (lane == 0) B = fmaf(A, carry, B);

    // truncated scan; last level needs B only
    float Au, Bu;
    Au = __shfl_up_sync(0xffffffffu, A, 1);
    Bu = __shfl_up_sync(0xffffffffu, B, 1);
    if (lane >= 1) { B = fmaf(A, Bu, B); A *= Au; }
    Au = __shfl_up_sync(0xffffffffu, A, 2);
    Bu = __shfl_up_sync(0xffffffffu, B, 2);
    if (lane >= 2) { B = fmaf(A, Bu, B); A *= Au; }
    Bu = __shfl_up_sync(0xffffffffu, B, 4);
    if (lane >= 4) { B = fmaf(A, Bu, B); }

    // rotate: lane l gets B_{(l-1) mod 32}
    float rot = __shfl_sync(0xffffffffu, B, (lane + 31) & 31);
    float v;
    if (lane == 0) { v = carry; carry = rot; }   // rot == B_31 == next carry
    else           { v = rot; }

    if (act) {
        float4 r;
        v = fmaf(a0, v, fmaf(-20.0f, a0, 12.5f)); r.x = v;
        v = fmaf(a1, v, fmaf(-20.0f, a1, 12.5f)); r.y = v;
        v = fmaf(a2, v, fmaf(-20.0f, a2, 12.5f)); r.z = v;
        v = fmaf(a3, v, fmaf(-20.0f, a3, 12.5f)); r.w = v;
        *(float4*)(o + t) = r;
    }
}

// Warp owns a 2x2 cell tile: 4 row-loads feed 4 cell scans.
// Block = 8 warps = 2(i-pairs) x 4(j-pairs) -> 4i x 8j cells; grid 32 x 64.
__global__ __launch_bounds__(256, 4) void sim_kernel(float* __restrict__ out) {
    const int lane = threadIdx.x & 31;
    const int w    = threadIdx.x >> 5;              // 0..7
    const int i0 = blockIdx.y * 4 + (w >> 2) * 2;
    const int j0 = blockIdx.x * 8 + (w & 3) * 2;

    const float* __restrict__ qi0 = g_q[0] + i0 * TT;
    const float* __restrict__ qi1 = qi0 + TT;
    const float* __restrict__ qj0 = g_q[1] + j0 * TT;
    const float* __restrict__ qj1 = qj0 + TT;

    float* __restrict__ o00 = out + (i0 * NN + j0) * TT;
    float* __restrict__ o01 = o00 + TT;
    float* __restrict__ o10 = o00 + NN * TT;
    float* __restrict__ o11 = o10 + TT;

    float c00 = 0.0f, c01 = 0.0f, c10 = 0.0f, c11 = 0.0f;

    #pragma unroll 1
    for (int c = 0; c < NCHUNK; c++) {
        const int t = c * CT + lane * R;
        const bool act = (t < TT);

        float4 x0, x1, y0, y1;
        if (act) {
            x0 = *(const float4*)(qi0 + t);
            x1 = *(const float4*)(qi1 + t);
            y0 = *(const float4*)(qj0 + t);
            y1 = *(const float4*)(qj1 + t);
        }

        cell_chunk(x0, y0, act, lane, c00, o00, t);
        cell_chunk(x0, y1, act, lane, c01, o01, t);
        cell_chunk(x1, y0, act, lane, c10, o10, t);
        cell_chunk(x1, y1, act, lane, c11, o11, t);
    }
}

extern "C" void kernel_launch(void* const* d_in, const int* in_sizes, int n_in,
                              void* d_out, int out_size) {
    const float* u0   = (const float*)d_in[0];   // u_pre_0 (N,T)
    const float* u1   = (const float*)d_in[1];   // u_pre_1 (N,T)
    const float* ksyn = (const float*)d_in[2];   // k_syn (2,N)
    float* out = (float*)d_out;                  // (N,N,T) fp32

    prep_kernel<<<(NN * TT / 4 + 255) / 256, 256>>>(u0, u1, ksyn);

    dim3 grid(NN / 8, NN / 4);                   // 32 x 64 = 2048 blocks
    sim_kernel<<<grid, 256>>>(out);
}